// round 2
// baseline (speedup 1.0000x reference)
#include <cuda_runtime.h>

// Problem constants (fixed by the reference):
//   B=2 batches, C=64 channels, N=1024 spatial, heads=64 -> head_dim=1.
// Algebraic collapse: out_b = (Wp diag(s_b) Wq) X_b + X_b,
//   s_b[c] = wk_c^T (X_b X_b^T) wv_c.

#define Bb 2
#define Cc 64
#define Nn 1024
#define NC 16   // n-chunks for Gram / final GEMM
#define TN 64   // columns per chunk

// Scratch (no allocations allowed): partial Grams + M^T per batch.
__device__ float g_partG[Bb * NC * Cc * Cc];   // 512 KB
__device__ float g_MT[Bb * Cc * Cc];           // M transposed: MT[k][o] = M[o][k]

// ---------------------------------------------------------------------------
// K1: partial Gram. Block (b, chunk): G_part[i][j] = sum_{n in chunk} X[i,n]X[j,n]
// 256 threads, each computes a 4x4 tile of the 64x64 Gram via float4 smem reads.
// ---------------------------------------------------------------------------
__global__ void __launch_bounds__(256) k_gram(const float* __restrict__ x) {
    const int b   = blockIdx.x >> 4;
    const int chq = blockIdx.x & 15;
    const int n0  = chq * TN;

    __shared__ __align__(16) float Xs[TN][68];   // [n][c], pad 68 -> bank-stride 4, 16B rows

    const int tid = threadIdx.x;
    const float* xb = x + b * Cc * Nn + n0;

    // Coalesced load of the 64x64 chunk; transpose into [n][c].
    #pragma unroll
    for (int k = 0; k < 16; k++) {
        int idx = tid + 256 * k;
        int c = idx >> 6, nl = idx & 63;
        Xs[nl][c] = xb[c * Nn + nl];
    }
    __syncthreads();

    const int ti = tid & 15;   // i-tile
    const int tj = tid >> 4;   // j-tile
    float acc[4][4] = {};

    #pragma unroll 4
    for (int n = 0; n < TN; n++) {
        float4 a4 = *(const float4*)&Xs[n][ti * 4];
        float4 b4 = *(const float4*)&Xs[n][tj * 4];
        float av[4] = {a4.x, a4.y, a4.z, a4.w};
        float bv[4] = {b4.x, b4.y, b4.z, b4.w};
        #pragma unroll
        for (int i = 0; i < 4; i++)
            #pragma unroll
            for (int j = 0; j < 4; j++)
                acc[i][j] += av[i] * bv[j];
    }

    float* gp = g_partG + ((size_t)blockIdx.x << 12);
    #pragma unroll
    for (int i = 0; i < 4; i++) {
        float4 v = make_float4(acc[i][0], acc[i][1], acc[i][2], acc[i][3]);
        *(float4*)&gp[(ti * 4 + i) * 64 + tj * 4] = v;
    }
}

// ---------------------------------------------------------------------------
// K2: per batch (2 blocks, 256 threads):
//   1) reduce 16 partial Grams -> Gs (smem)
//   2) s[c] = sum_i wv[c,i] * (sum_j wk[c,j] * G[j,i])     (4 threads per c)
//   3) MT[k][o] = sum_c wp[o,c] * s[c] * wq[c,k]           (4x4 register tiles)
// ---------------------------------------------------------------------------
__global__ void __launch_bounds__(256) k_mid(const float* __restrict__ wq,
                                             const float* __restrict__ wk,
                                             const float* __restrict__ wv,
                                             const float* __restrict__ wp) {
    const int b = blockIdx.x;
    __shared__ __align__(16) float Gs[64][68];
    __shared__ float Ss[64];
    const int tid = threadIdx.x;

    // Reduce the 16 partial Grams.
    #pragma unroll
    for (int k = 0; k < 16; k++) {
        int e = tid + 256 * k;
        float acc = 0.f;
        #pragma unroll
        for (int ch = 0; ch < NC; ch++)
            acc += g_partG[(((size_t)(b * NC + ch)) << 12) + e];
        Gs[e >> 6][e & 63] = acc;
    }
    __syncthreads();

    // s[c] with 4 threads per channel c (each handles 16 of the i's).
    {
        const int c = tid >> 2;
        const int q = tid & 3;
        const float* wkc = wk + c * 64;
        const float* wvc = wv + c * 64;
        float acc[16] = {};
        #pragma unroll 4
        for (int j = 0; j < 64; j++) {
            float wkj = __ldg(&wkc[j]);
            #pragma unroll
            for (int ii = 0; ii < 16; ii++)
                acc[ii] += wkj * Gs[j][q * 16 + ii];
        }
        float part = 0.f;
        #pragma unroll
        for (int ii = 0; ii < 16; ii++)
            part += acc[ii] * __ldg(&wvc[q * 16 + ii]);
        part += __shfl_down_sync(0xffffffffu, part, 2);
        part += __shfl_down_sync(0xffffffffu, part, 1);
        if (q == 0) Ss[c] = part;
    }
    __syncthreads();

    // M[o,k] = sum_c wp[o,c]*s[c]*wq[c,k]; store transposed as MT[k][o].
    const int to = tid & 15;   // o-tile
    const int tk = tid >> 4;   // k-tile
    float acc2[4][4] = {};     // [oo][kk]
    #pragma unroll 4
    for (int c = 0; c < 64; c++) {
        float sc = Ss[c];
        float pw[4];
        #pragma unroll
        for (int oo = 0; oo < 4; oo++)
            pw[oo] = __ldg(&wp[(to * 4 + oo) * 64 + c]) * sc;
        float4 q4 = *(const float4*)&wq[c * 64 + tk * 4];
        float qv[4] = {q4.x, q4.y, q4.z, q4.w};
        #pragma unroll
        for (int oo = 0; oo < 4; oo++)
            #pragma unroll
            for (int kk = 0; kk < 4; kk++)
                acc2[oo][kk] += pw[oo] * qv[kk];
    }
    float* mt = g_MT + ((size_t)b << 12);
    #pragma unroll
    for (int kk = 0; kk < 4; kk++) {
        float4 v = make_float4(acc2[0][kk], acc2[1][kk], acc2[2][kk], acc2[3][kk]);
        *(float4*)&mt[(tk * 4 + kk) * 64 + to * 4] = v;
    }
}

// ---------------------------------------------------------------------------
// K3: out[b,o,n] = sum_c M[o,c] X[b,c,n] + X[b,o,n].
// Block (b, chunk of 64 n). 4x4 register tiles, float4 smem reads of MT and X.
// ---------------------------------------------------------------------------
__global__ void __launch_bounds__(256) k_final(const float* __restrict__ x,
                                               float* __restrict__ out) {
    const int b   = blockIdx.x >> 4;
    const int chq = blockIdx.x & 15;
    const int n0  = chq * TN;

    __shared__ __align__(16) float Xs[64][68];    // [c][n]
    __shared__ __align__(16) float Mts[64][68];   // [c][o] (M transposed)

    const int tid = threadIdx.x;
    const float* xb = x + b * Cc * Nn + n0;
    const float* mt = g_MT + ((size_t)b << 12);

    #pragma unroll
    for (int k = 0; k < 16; k++) {
        int idx = tid + 256 * k;
        int r = idx >> 6, cl = idx & 63;
        Xs[r][cl]  = xb[r * Nn + cl];
        Mts[r][cl] = mt[idx];
    }
    __syncthreads();

    const int to = tid & 15;   // o-tile
    const int tn = tid >> 4;   // n-tile
    float acc[4][4] = {};      // [oo][nn]

    #pragma unroll 4
    for (int c = 0; c < 64; c++) {
        float4 m4 = *(const float4*)&Mts[c][to * 4];
        float4 x4 = *(const float4*)&Xs[c][tn * 4];
        float mv[4] = {m4.x, m4.y, m4.z, m4.w};
        float xv[4] = {x4.x, x4.y, x4.z, x4.w};
        #pragma unroll
        for (int oo = 0; oo < 4; oo++)
            #pragma unroll
            for (int nn = 0; nn < 4; nn++)
                acc[oo][nn] += mv[oo] * xv[nn];
    }

    float* ob = out + b * Cc * Nn + n0;
    #pragma unroll
    for (int oo = 0; oo < 4; oo++) {
        int o = to * 4 + oo;
        float4 r;
        r.x = acc[oo][0] + Xs[o][tn * 4 + 0];
        r.y = acc[oo][1] + Xs[o][tn * 4 + 1];
        r.z = acc[oo][2] + Xs[o][tn * 4 + 2];
        r.w = acc[oo][3] + Xs[o][tn * 4 + 3];
        *(float4*)&ob[o * Nn + tn * 4] = r;
    }
}

extern "C" void kernel_launch(void* const* d_in, const int* in_sizes, int n_in,
                              void* d_out, int out_size) {
    const float* x  = (const float*)d_in[0];
    const float* wq = (const float*)d_in[1];
    const float* wk = (const float*)d_in[2];
    const float* wv = (const float*)d_in[3];
    const float* wp = (const float*)d_in[4];
    float* out = (float*)d_out;

    k_gram <<<Bb * NC, 256>>>(x);
    k_mid  <<<Bb,      256>>>(wq, wk, wv, wp);
    k_final<<<Bb * NC, 256>>>(x, out);
}

// round 3
// speedup vs baseline: 2.9520x; 2.9520x over previous
#include <cuda_runtime.h>

// Problem constants (fixed by the reference):
//   B=2, C=64 channels/heads (head_dim=1), N=1024 spatial, SCALE=1.
// Algebraic collapse:
//   s_b[c]   = sum_n (Wk X_b)[c,n] * (Wv X_b)[c,n]
//   M_b[o,k] = sum_h wp[o,h] * s_b[h] * wq[h,k]
//   out_b    = M_b X_b + X_b
//
// Single kernel, 128 blocks (one wave on 148 SMs), 2 grid-wide spin barriers.
// TN = 16 spatial columns per block; 64 chunks per batch.

#define NBLK 128
#define NTHR 256

// Cross-block scratch (static device globals; no allocations).
__device__ float g_sPart[NBLK][64];     // per-chunk partial s
__device__ float g_MT[2][64 * 64];      // M transposed: MT[k*64+o] = M[o][k]

// Replay-safe grid barrier: counter is reset to 0 by the releaser BEFORE the
// monotonic flag is bumped, so every launch starts with cnt==0 and any flag
// value. Each slot is used exactly once per launch.
__device__ unsigned g_cnt[2];
__device__ volatile unsigned g_flag[2];

__device__ __forceinline__ void gridbar(int i) {
    __syncthreads();
    if (threadIdx.x == 0) {
        unsigned f0 = g_flag[i];            // pre-release value (stable: we haven't arrived)
        __threadfence();                    // publish this block's global writes
        unsigned old = atomicAdd(&g_cnt[i], 1u);
        if (old == NBLK - 1) {
            g_cnt[i] = 0;                   // reset for next launch
            __threadfence();
            atomicAdd((unsigned*)&g_flag[i], 1u);   // release
        } else {
            while (g_flag[i] == f0) { __nanosleep(40); }
        }
        __threadfence();                    // acquire
    }
    __syncthreads();
}

struct SmemA { float Wks[64][68]; float Wvs[64][68]; };
struct SmemD { float Wqs[64][68]; float s[64]; };
struct SmemE { float Mts[64][68]; };
union  SmemU { SmemA a; SmemD d; SmemE e; };

__global__ void __launch_bounds__(NTHR) attn_fused(
    const float* __restrict__ x,
    const float* __restrict__ wq, const float* __restrict__ wk,
    const float* __restrict__ wv, const float* __restrict__ wp,
    float* __restrict__ out)
{
    __shared__ SmemU su;
    __shared__ float Xt[64][17];        // [c][n_local], persists phase A -> C

    const int tid = threadIdx.x;
    const int blk = blockIdx.x;
    const int b   = blk >> 6;           // batch
    const int ch  = blk & 63;           // chunk
    const int n0  = ch * 16;

    // ---------------- Phase A: load X chunk + Wk/Wv, compute partial s -----
    {
        const float* xb = x + b * 65536 + n0;
        #pragma unroll
        for (int k = 0; k < 4; k++) {               // 1024 elems
            int e = tid + 256 * k;
            int c = e >> 4, n = e & 15;
            Xt[c][n] = xb[c * 1024 + n];
        }
        #pragma unroll
        for (int k = 0; k < 16; k++) {              // 4096 elems each
            int e = tid + 256 * k;
            int c = e >> 6, j = e & 63;
            su.a.Wks[c][j] = wk[e];
            su.a.Wvs[c][j] = wv[e];
        }
        __syncthreads();

        const int tc = tid >> 4;        // channel tile (4 channels)
        const int tn = tid & 15;        // spatial column
        float accK[4] = {}, accV[4] = {};

        #pragma unroll
        for (int j4 = 0; j4 < 16; j4++) {
            float xv0 = Xt[j4 * 4 + 0][tn];
            float xv1 = Xt[j4 * 4 + 1][tn];
            float xv2 = Xt[j4 * 4 + 2][tn];
            float xv3 = Xt[j4 * 4 + 3][tn];
            #pragma unroll
            for (int cc = 0; cc < 4; cc++) {
                const int c = tc * 4 + cc;
                float4 kw = *(const float4*)&su.a.Wks[c][j4 * 4];
                float4 vw = *(const float4*)&su.a.Wvs[c][j4 * 4];
                accK[cc] += kw.x * xv0 + kw.y * xv1 + kw.z * xv2 + kw.w * xv3;
                accV[cc] += vw.x * xv0 + vw.y * xv1 + vw.z * xv2 + vw.w * xv3;
            }
        }

        // s partial over this chunk's 16 columns: reduce within 16-lane group
        // (lanes of a half-warp share tc) -> deterministic shuffle tree.
        #pragma unroll
        for (int cc = 0; cc < 4; cc++) {
            float v = accK[cc] * accV[cc];
            v += __shfl_down_sync(0xffffffffu, v, 8, 16);
            v += __shfl_down_sync(0xffffffffu, v, 4, 16);
            v += __shfl_down_sync(0xffffffffu, v, 2, 16);
            v += __shfl_down_sync(0xffffffffu, v, 1, 16);
            if (tn == 0) g_sPart[blk][tc * 4 + cc] = v;
        }
    }

    gridbar(0);

    // ---------------- Phase B (blocks 0..15): build M^T ---------------------
    if (blk < 16) {
        const int mb = blk >> 3;        // batch for M
        const int og = blk & 7;         // o-row group (8 rows)

        // Reduce s (deterministic fixed-order sum).
        if (tid < 64) {
            float s = 0.f;
            #pragma unroll 8
            for (int c2 = 0; c2 < 64; c2++)
                s += __ldcg(&g_sPart[mb * 64 + c2][tid]);
            su.d.s[tid] = s;
        }
        // Stage Wq.
        #pragma unroll
        for (int k = 0; k < 16; k++) {
            int e = tid + 256 * k;
            su.d.Wqs[e >> 6][e & 63] = wq[e];
        }
        __syncthreads();

        const int w    = tid >> 5;              // warp -> one o row
        const int lane = tid & 31;              // lane -> 2 k columns
        const int o    = og * 8 + w;
        float m0 = 0.f, m1 = 0.f;
        #pragma unroll 8
        for (int c = 0; c < 64; c++) {
            float a  = __ldg(&wp[o * 64 + c]) * su.d.s[c];
            float2 q2 = *(const float2*)&su.d.Wqs[c][lane * 2];
            m0 += a * q2.x;
            m1 += a * q2.y;
        }
        g_MT[mb][(2 * lane + 0) * 64 + o] = m0;
        g_MT[mb][(2 * lane + 1) * 64 + o] = m1;
    }

    gridbar(1);

    // ---------------- Phase C: out = M X + X (X tile still in smem) --------
    {
        #pragma unroll
        for (int k = 0; k < 16; k++) {
            int e = tid + 256 * k;
            su.e.Mts[e >> 6][e & 63] = __ldcg(&g_MT[b][e]);
        }
        __syncthreads();

        const int tc = tid >> 4;        // o tile (4 rows)
        const int tn = tid & 15;        // spatial column
        float acc[4] = {};
        #pragma unroll
        for (int k = 0; k < 64; k++) {
            float xk  = Xt[k][tn];
            float4 m4 = *(const float4*)&su.e.Mts[k][tc * 4];
            acc[0] += m4.x * xk;
            acc[1] += m4.y * xk;
            acc[2] += m4.z * xk;
            acc[3] += m4.w * xk;
        }
        float* ob = out + b * 65536 + n0;
        #pragma unroll
        for (int oo = 0; oo < 4; oo++) {
            int o = tc * 4 + oo;
            ob[o * 1024 + tn] = acc[oo] + Xt[o][tn];
        }
    }
}

extern "C" void kernel_launch(void* const* d_in, const int* in_sizes, int n_in,
                              void* d_out, int out_size) {
    const float* x  = (const float*)d_in[0];
    const float* wq = (const float*)d_in[1];
    const float* wk = (const float*)d_in[2];
    const float* wv = (const float*)d_in[3];
    const float* wp = (const float*)d_in[4];
    attn_fused<<<NBLK, NTHR>>>(x, wq, wk, wv, wp, (float*)d_out);
}

// round 4
// speedup vs baseline: 3.5635x; 1.2071x over previous
#include <cuda_runtime.h>

// out_b = Wp (s_b ∘ (Wq X_b)) + X_b,  s_b[c] = sum_n (Wk X_b)[c,n]*(Wv X_b)[c,n]
// B=2, C=64, N=1024. 128 blocks x 256 threads, ONE grid barrier.
// Each block owns 16 spatial columns; X tile lives in smem for the whole kernel.

#define NBLK 128
#define NTHR 256

__device__ float g_sPart[2][64][64];          // [batch][channel][chunk]

// Replay-safe grid barrier (monotonic flag; counter reset before release).
__device__ unsigned g_cnt;
__device__ volatile unsigned g_flag;

__device__ __forceinline__ void gridbar() {
    __syncthreads();                          // also drains pending STS
    if (threadIdx.x == 0) {
        unsigned f0 = g_flag;
        __threadfence();
        unsigned old = atomicAdd(&g_cnt, 1u);
        if (old == NBLK - 1) {
            g_cnt = 0;
            __threadfence();
            atomicAdd((unsigned*)&g_flag, 1u);
        } else {
            while (g_flag == f0) { __nanosleep(20); }
        }
        __threadfence();
    }
    __syncthreads();
}

// Weight region: phase A holds {Wk,Wv}, phase B holds {Wq,Wp}. 32 KB.
union SmemW {
    struct { float k[64 * 64]; float v[64 * 64]; } a;
    struct { float q[64 * 64]; float p[64 * 64]; } b;
};

__global__ void __launch_bounds__(NTHR) attn_fused(
    const float* __restrict__ x,
    const float* __restrict__ wq, const float* __restrict__ wk,
    const float* __restrict__ wv, const float* __restrict__ wp,
    float* __restrict__ out)
{
    __shared__ SmemW sw;
    __shared__ __align__(16) float Xt[64][17];   // [c][n_local]
    __shared__ __align__(16) float Ys[64][17];   // s-scaled Wq·X
    __shared__ float Ssh[64];

    const int tid = threadIdx.x;
    const int blk = blockIdx.x;
    const int b   = blk >> 6;
    const int ch  = blk & 63;
    const int n0  = ch * 16;

    const int tc = tid >> 4;                  // 4-channel tile
    const int tn = tid & 15;                  // spatial column

    // ---- Load X chunk + Wk/Wv ------------------------------------------------
    const float* xb = x + b * 65536 + n0;
    #pragma unroll
    for (int k = 0; k < 4; k++) {
        int e = tid + 256 * k;
        Xt[e >> 4][e & 15] = xb[(e >> 4) * 1024 + (e & 15)];
    }
    #pragma unroll
    for (int k = 0; k < 16; k++) {
        int e = tid + 256 * k;
        sw.a.k[e] = wk[e];
        sw.a.v[e] = wv[e];
    }
    __syncthreads();

    // ---- Phase A: partial s over this chunk ---------------------------------
    {
        float accK[4] = {}, accV[4] = {};
        #pragma unroll
        for (int j4 = 0; j4 < 16; j4++) {
            float xv0 = Xt[j4 * 4 + 0][tn];
            float xv1 = Xt[j4 * 4 + 1][tn];
            float xv2 = Xt[j4 * 4 + 2][tn];
            float xv3 = Xt[j4 * 4 + 3][tn];
            #pragma unroll
            for (int cc = 0; cc < 4; cc++) {
                const int c = tc * 4 + cc;
                float4 kw = *(const float4*)&sw.a.k[c * 64 + j4 * 4];
                float4 vw = *(const float4*)&sw.a.v[c * 64 + j4 * 4];
                accK[cc] += kw.x * xv0 + kw.y * xv1 + kw.z * xv2 + kw.w * xv3;
                accV[cc] += vw.x * xv0 + vw.y * xv1 + vw.z * xv2 + vw.w * xv3;
            }
        }
        #pragma unroll
        for (int cc = 0; cc < 4; cc++) {
            float v = accK[cc] * accV[cc];
            v += __shfl_down_sync(0xffffffffu, v, 8, 16);
            v += __shfl_down_sync(0xffffffffu, v, 4, 16);
            v += __shfl_down_sync(0xffffffffu, v, 2, 16);
            v += __shfl_down_sync(0xffffffffu, v, 1, 16);
            if (tn == 0) g_sPart[b][tc * 4 + cc][ch] = v;
        }
    }

    // ---- Stage Wq/Wp over the dead Wk/Wv region (overlaps barrier skew) -----
    __syncthreads();                          // everyone done reading Wk/Wv
    #pragma unroll
    for (int k = 0; k < 16; k++) {
        int e = tid + 256 * k;
        sw.b.q[e] = wq[e];
        sw.b.p[e] = wp[e];
    }

    gridbar();

    // ---- Reduce s (deterministic fixed-order, 4 threads/channel) ------------
    {
        const int c = tid >> 2, q = tid & 3;
        const float* sp = &g_sPart[b][c][q * 16];
        float v = 0.f;
        #pragma unroll
        for (int j = 0; j < 16; j++) v += __ldcg(&sp[j]);
        v += __shfl_down_sync(0xffffffffu, v, 2, 4);
        v += __shfl_down_sync(0xffffffffu, v, 1, 4);
        if (q == 0) Ssh[c] = v;
    }
    __syncthreads();

    // ---- Ys = s ∘ (Wq · Xt) --------------------------------------------------
    {
        float acc[4] = {};
        #pragma unroll
        for (int j4 = 0; j4 < 16; j4++) {
            float xv0 = Xt[j4 * 4 + 0][tn];
            float xv1 = Xt[j4 * 4 + 1][tn];
            float xv2 = Xt[j4 * 4 + 2][tn];
            float xv3 = Xt[j4 * 4 + 3][tn];
            #pragma unroll
            for (int cc = 0; cc < 4; cc++) {
                float4 qw = *(const float4*)&sw.b.q[(tc * 4 + cc) * 64 + j4 * 4];
                acc[cc] += qw.x * xv0 + qw.y * xv1 + qw.z * xv2 + qw.w * xv3;
            }
        }
        #pragma unroll
        for (int cc = 0; cc < 4; cc++)
            Ys[tc * 4 + cc][tn] = acc[cc] * Ssh[tc * 4 + cc];
    }
    __syncthreads();

    // ---- out = Wp · Ys + Xt --------------------------------------------------
    {
        float acc[4] = {};
        #pragma unroll
        for (int j4 = 0; j4 < 16; j4++) {
            float yv0 = Ys[j4 * 4 + 0][tn];
            float yv1 = Ys[j4 * 4 + 1][tn];
            float yv2 = Ys[j4 * 4 + 2][tn];
            float yv3 = Ys[j4 * 4 + 3][tn];
            #pragma unroll
            for (int oo = 0; oo < 4; oo++) {
                float4 pw = *(const float4*)&sw.b.p[(tc * 4 + oo) * 64 + j4 * 4];
                acc[oo] += pw.x * yv0 + pw.y * yv1 + pw.z * yv2 + pw.w * yv3;
            }
        }
        float* ob = out + b * 65536 + n0;
        #pragma unroll
        for (int oo = 0; oo < 4; oo++) {
            const int o = tc * 4 + oo;
            ob[o * 1024 + tn] = acc[oo] + Xt[o][tn];
        }
    }
}

extern "C" void kernel_launch(void* const* d_in, const int* in_sizes, int n_in,
                              void* d_out, int out_size) {
    const float* x  = (const float*)d_in[0];
    const float* wq = (const float*)d_in[1];
    const float* wk = (const float*)d_in[2];
    const float* wv = (const float*)d_in[3];
    const float* wp = (const float*)d_in[4];
    attn_fused<<<NBLK, NTHR>>>(x, wq, wk, wv, wp, (float*)d_out);
}

// round 5
// speedup vs baseline: 3.5794x; 1.0045x over previous
#include <cuda_runtime.h>

// out_b = Wp (s_b ∘ (Wq X_b)) + X_b,  s_b[c] = sum_n (Wk X_b)[c,n]*(Wv X_b)[c,n]
// B=2, C=64, N=1024. 128 blocks x 512 threads (16 warps/SM), ONE grid barrier.
// Each block owns 16 spatial columns; X tile persists in smem.

#define NBLK 128
#define NTHR 512

__device__ float g_sPart[2][64][64];          // [batch][channel][chunk]

// Replay-safe grid barrier (monotonic flag; counter reset before release).
__device__ unsigned g_cnt;
__device__ volatile unsigned g_flag;

__device__ __forceinline__ void gridbar() {
    __syncthreads();                          // drains pending STS/STG ordering
    if (threadIdx.x == 0) {
        unsigned f0 = g_flag;
        __threadfence();
        unsigned old = atomicAdd(&g_cnt, 1u);
        if (old == NBLK - 1) {
            g_cnt = 0;
            __threadfence();
            atomicAdd((unsigned*)&g_flag, 1u);
        } else {
            while (g_flag == f0) { }          // hot spin; wake = one L2 trip
        }
        __threadfence();
    }
    __syncthreads();
}

// Weight region: phase A holds {Wk,Wv}, phase B holds {Wq,Wp}. 32 KB.
union SmemW {
    struct { float k[64 * 64]; float v[64 * 64]; } a;
    struct { float q[64 * 64]; float p[64 * 64]; } b;
};

__global__ void __launch_bounds__(NTHR) attn_fused(
    const float* __restrict__ x,
    const float* __restrict__ wq, const float* __restrict__ wk,
    const float* __restrict__ wv, const float* __restrict__ wp,
    float* __restrict__ out)
{
    __shared__ SmemW sw;
    __shared__ __align__(16) float Xt[64][17];   // [c][n_local]
    __shared__ __align__(16) float Ys[64][17];   // s-scaled Wq·X
    __shared__ float Ssh[64];

    const int tid = threadIdx.x;
    const int blk = blockIdx.x;
    const int b   = blk >> 6;
    const int ch  = blk & 63;
    const int n0  = ch * 16;

    const int tn = tid & 15;                  // spatial column
    const int tc = tid >> 4;                  // 2-channel tile (0..31)
    const int c0 = tc * 2;

    // ---- Load X chunk + Wk/Wv -----------------------------------------------
    const float* xb = x + b * 65536 + n0;
    #pragma unroll
    for (int k = 0; k < 2; k++) {
        int e = tid + NTHR * k;
        Xt[e >> 4][e & 15] = xb[(e >> 4) * 1024 + (e & 15)];
    }
    #pragma unroll
    for (int k = 0; k < 8; k++) {
        int e = tid + NTHR * k;
        sw.a.k[e] = wk[e];
        sw.a.v[e] = wv[e];
    }
    __syncthreads();

    // ---- Phase A: partial s over this chunk ---------------------------------
    {
        float accK[2] = {}, accV[2] = {};
        #pragma unroll
        for (int j4 = 0; j4 < 16; j4++) {
            float xv0 = Xt[j4 * 4 + 0][tn];
            float xv1 = Xt[j4 * 4 + 1][tn];
            float xv2 = Xt[j4 * 4 + 2][tn];
            float xv3 = Xt[j4 * 4 + 3][tn];
            #pragma unroll
            for (int cc = 0; cc < 2; cc++) {
                const int c = c0 + cc;
                float4 kw = *(const float4*)&sw.a.k[c * 64 + j4 * 4];
                float4 vw = *(const float4*)&sw.a.v[c * 64 + j4 * 4];
                accK[cc] += kw.x * xv0 + kw.y * xv1 + kw.z * xv2 + kw.w * xv3;
                accV[cc] += vw.x * xv0 + vw.y * xv1 + vw.z * xv2 + vw.w * xv3;
            }
        }
        #pragma unroll
        for (int cc = 0; cc < 2; cc++) {
            float v = accK[cc] * accV[cc];
            v += __shfl_down_sync(0xffffffffu, v, 8, 16);
            v += __shfl_down_sync(0xffffffffu, v, 4, 16);
            v += __shfl_down_sync(0xffffffffu, v, 2, 16);
            v += __shfl_down_sync(0xffffffffu, v, 1, 16);
            if (tn == 0) g_sPart[b][c0 + cc][ch] = v;
        }
    }

    // ---- Stage Wq/Wp over the dead Wk/Wv region (before arriving) -----------
    __syncthreads();                          // everyone done reading Wk/Wv
    #pragma unroll
    for (int k = 0; k < 8; k++) {
        int e = tid + NTHR * k;
        sw.b.q[e] = wq[e];
        sw.b.p[e] = wp[e];
    }

    gridbar();

    // ---- Reduce s (deterministic fixed-order, 8 threads/channel) ------------
    {
        const int c = tid >> 3, q = tid & 7;
        const float* sp = &g_sPart[b][c][q * 8];
        float v = 0.f;
        #pragma unroll
        for (int j = 0; j < 8; j++) v += __ldcg(&sp[j]);
        v += __shfl_down_sync(0xffffffffu, v, 4, 8);
        v += __shfl_down_sync(0xffffffffu, v, 2, 8);
        v += __shfl_down_sync(0xffffffffu, v, 1, 8);
        if (q == 0) Ssh[c] = v;
    }
    __syncthreads();

    // ---- Ys = s ∘ (Wq · Xt) --------------------------------------------------
    {
        float acc[2] = {};
        #pragma unroll
        for (int j4 = 0; j4 < 16; j4++) {
            float xv0 = Xt[j4 * 4 + 0][tn];
            float xv1 = Xt[j4 * 4 + 1][tn];
            float xv2 = Xt[j4 * 4 + 2][tn];
            float xv3 = Xt[j4 * 4 + 3][tn];
            #pragma unroll
            for (int cc = 0; cc < 2; cc++) {
                float4 qw = *(const float4*)&sw.b.q[(c0 + cc) * 64 + j4 * 4];
                acc[cc] += qw.x * xv0 + qw.y * xv1 + qw.z * xv2 + qw.w * xv3;
            }
        }
        #pragma unroll
        for (int cc = 0; cc < 2; cc++)
            Ys[c0 + cc][tn] = acc[cc] * Ssh[c0 + cc];
    }
    __syncthreads();

    // ---- out = Wp · Ys + Xt --------------------------------------------------
    {
        float acc[2] = {};
        #pragma unroll
        for (int j4 = 0; j4 < 16; j4++) {
            float yv0 = Ys[j4 * 4 + 0][tn];
            float yv1 = Ys[j4 * 4 + 1][tn];
            float yv2 = Ys[j4 * 4 + 2][tn];
            float yv3 = Ys[j4 * 4 + 3][tn];
            #pragma unroll
            for (int oo = 0; oo < 2; oo++) {
                float4 pw = *(const float4*)&sw.b.p[(c0 + oo) * 64 + j4 * 4];
                acc[oo] += pw.x * yv0 + pw.y * yv1 + pw.z * yv2 + pw.w * yv3;
            }
        }
        float* ob = out + b * 65536 + n0;
        #pragma unroll
        for (int oo = 0; oo < 2; oo++) {
            const int o = c0 + oo;
            ob[o * 1024 + tn] = acc[oo] + Xt[o][tn];
        }
    }
}

extern "C" void kernel_launch(void* const* d_in, const int* in_sizes, int n_in,
                              void* d_out, int out_size) {
    const float* x  = (const float*)d_in[0];
    const float* wq = (const float*)d_in[1];
    const float* wk = (const float*)d_in[2];
    const float* wv = (const float*)d_in[3];
    const float* wp = (const float*)d_in[4];
    attn_fused<<<NBLK, NTHR>>>(x, wq, wk, wv, wp, (float*)d_out);
}

// round 6
// speedup vs baseline: 3.8554x; 1.0771x over previous
#include <cuda_runtime.h>

// out_b = Wp (s_b ∘ (Wq X_b)) + X_b,  s_b[c] = sum_n (Wk X_b)[c,n]*(Wv X_b)[c,n]
// B=2, C=64, N=1024. 128 blocks x 512 threads, one wave, ONE grid barrier.
// Each block owns 16 spatial columns. K/V/Q projections fused in one X pass,
// Y=Wq·X computed pre-barrier; post-barrier only: reduce s, scale Ys, Wp GEMM.

#define NBLK 128
#define NTHR 512

// smem layout (floats): Wk[4096] Wv[4096] Wq[4096] Wp[4096] Xt[16*68] Ys[16*68] Ssh[64]
#define OFF_WK 0
#define OFF_WV 4096
#define OFF_WQ 8192
#define OFF_WP 12288
#define OFF_XT 16384
#define OFF_YS (16384 + 16*68)
#define OFF_SS (16384 + 32*68)
#define SMEM_FLOATS (OFF_SS + 64)

__device__ float g_sPart[2][64][64];          // [batch][channel][chunk]

// Replay-safe grid barrier (monotonic flag; counter reset before release).
__device__ unsigned g_cnt;
__device__ volatile unsigned g_flag;

__device__ __forceinline__ void gridbar() {
    __syncthreads();
    if (threadIdx.x == 0) {
        unsigned f0 = g_flag;
        __threadfence();
        unsigned old = atomicAdd(&g_cnt, 1u);
        if (old == NBLK - 1) {
            g_cnt = 0;
            __threadfence();
            atomicAdd((unsigned*)&g_flag, 1u);
        } else {
            while (g_flag == f0) { }
        }
        __threadfence();
    }
    __syncthreads();
}

extern __shared__ float sm[];

__global__ void __launch_bounds__(NTHR) attn_fused(
    const float* __restrict__ x,
    const float* __restrict__ wq, const float* __restrict__ wk,
    const float* __restrict__ wv, const float* __restrict__ wp,
    float* __restrict__ out)
{
    const int tid = threadIdx.x;
    const int blk = blockIdx.x;
    const int b   = blk >> 6;
    const int ch  = blk & 63;
    const int n0  = ch * 16;

    const int tn = tid & 15;                  // spatial column (0..15)
    const int c0 = (tid >> 4) * 2;            // 2-channel tile

    float* Wk = sm + OFF_WK;
    float* Wv = sm + OFF_WV;
    float* Wq = sm + OFF_WQ;
    float* Wp = sm + OFF_WP;
    float* Xt = sm + OFF_XT;                  // [n][c] stride 68
    float* Ys = sm + OFF_YS;                  // [n][c] stride 68
    float* Ss = sm + OFF_SS;

    // ---- Stage all weights (vectorized) + X chunk (transposed) -------------
    {
        float4*       s4  = (float4*)sm;
        const float4* k4  = (const float4*)wk;
        const float4* v4  = (const float4*)wv;
        const float4* q4  = (const float4*)wq;
        const float4* p4  = (const float4*)wp;
        #pragma unroll
        for (int i = 0; i < 2; i++) {
            int e = tid + NTHR * i;
            s4[e]        = k4[e];
            s4[1024 + e] = v4[e];
            s4[2048 + e] = q4[e];
            s4[3072 + e] = p4[e];
        }
        const float* xb = x + b * 65536 + n0;
        #pragma unroll
        for (int i = 0; i < 2; i++) {
            int e = tid + NTHR * i;           // e = c*16 + n
            int c = e >> 4, n = e & 15;
            Xt[n * 68 + c] = xb[c * 1024 + n];
        }
    }
    __syncthreads();

    // ---- Fused K/V/Q projections: one pass over X --------------------------
    {
        const float* XtR = Xt + tn * 68;
        float aK0 = 0.f, aK1 = 0.f, aV0 = 0.f, aV1 = 0.f, aQ0 = 0.f, aQ1 = 0.f;
        #pragma unroll
        for (int j = 0; j < 64; j += 4) {
            float4 x4 = *(const float4*)&XtR[j];
            float4 k0 = *(const float4*)&Wk[c0 * 64 + j];
            float4 k1 = *(const float4*)&Wk[(c0 + 1) * 64 + j];
            float4 v0 = *(const float4*)&Wv[c0 * 64 + j];
            float4 v1 = *(const float4*)&Wv[(c0 + 1) * 64 + j];
            float4 q0 = *(const float4*)&Wq[c0 * 64 + j];
            float4 q1 = *(const float4*)&Wq[(c0 + 1) * 64 + j];
            aK0 += k0.x * x4.x + k0.y * x4.y + k0.z * x4.z + k0.w * x4.w;
            aK1 += k1.x * x4.x + k1.y * x4.y + k1.z * x4.z + k1.w * x4.w;
            aV0 += v0.x * x4.x + v0.y * x4.y + v0.z * x4.z + v0.w * x4.w;
            aV1 += v1.x * x4.x + v1.y * x4.y + v1.z * x4.z + v1.w * x4.w;
            aQ0 += q0.x * x4.x + q0.y * x4.y + q0.z * x4.z + q0.w * x4.w;
            aQ1 += q1.x * x4.x + q1.y * x4.y + q1.z * x4.z + q1.w * x4.w;
        }
        // Unscaled Y into smem (scaled after the barrier).
        Ys[tn * 68 + c0]     = aQ0;
        Ys[tn * 68 + c0 + 1] = aQ1;

        // s partials: reduce over this chunk's 16 columns (16-lane groups).
        float v0 = aK0 * aV0, v1 = aK1 * aV1;
        v0 += __shfl_down_sync(0xffffffffu, v0, 8, 16);
        v1 += __shfl_down_sync(0xffffffffu, v1, 8, 16);
        v0 += __shfl_down_sync(0xffffffffu, v0, 4, 16);
        v1 += __shfl_down_sync(0xffffffffu, v1, 4, 16);
        v0 += __shfl_down_sync(0xffffffffu, v0, 2, 16);
        v1 += __shfl_down_sync(0xffffffffu, v1, 2, 16);
        v0 += __shfl_down_sync(0xffffffffu, v0, 1, 16);
        v1 += __shfl_down_sync(0xffffffffu, v1, 1, 16);
        if (tn == 0) {
            g_sPart[b][c0][ch]     = v0;
            g_sPart[b][c0 + 1][ch] = v1;
        }
    }

    gridbar();

    // ---- Reduce s (deterministic fixed-order, 8 threads/channel) -----------
    {
        const int c = tid >> 3, q = tid & 7;
        const float* sp = &g_sPart[b][c][q * 8];
        float v = 0.f;
        #pragma unroll
        for (int j = 0; j < 8; j++) v += __ldcg(&sp[j]);
        v += __shfl_down_sync(0xffffffffu, v, 4, 8);
        v += __shfl_down_sync(0xffffffffu, v, 2, 8);
        v += __shfl_down_sync(0xffffffffu, v, 1, 8);
        if (q == 0) Ss[c] = v;
    }
    __syncthreads();

    // ---- Scale Ys in place --------------------------------------------------
    Ys[tn * 68 + c0]     *= Ss[c0];
    Ys[tn * 68 + c0 + 1] *= Ss[c0 + 1];
    __syncthreads();

    // ---- out = Wp · Ys + X --------------------------------------------------
    {
        const float* YsR = Ys + tn * 68;
        float o0 = 0.f, o1 = 0.f;
        #pragma unroll
        for (int j = 0; j < 64; j += 4) {
            float4 y4 = *(const float4*)&YsR[j];
            float4 p0 = *(const float4*)&Wp[c0 * 64 + j];
            float4 p1 = *(const float4*)&Wp[(c0 + 1) * 64 + j];
            o0 += p0.x * y4.x + p0.y * y4.y + p0.z * y4.z + p0.w * y4.w;
            o1 += p1.x * y4.x + p1.y * y4.y + p1.z * y4.z + p1.w * y4.w;
        }
        float* ob = out + b * 65536 + n0;
        ob[c0 * 1024 + tn]       = o0 + Xt[tn * 68 + c0];
        ob[(c0 + 1) * 1024 + tn] = o1 + Xt[tn * 68 + c0 + 1];
    }
}

extern "C" void kernel_launch(void* const* d_in, const int* in_sizes, int n_in,
                              void* d_out, int out_size) {
    const float* x  = (const float*)d_in[0];
    const float* wq = (const float*)d_in[1];
    const float* wk = (const float*)d_in[2];
    const float* wv = (const float*)d_in[3];
    const float* wp = (const float*)d_in[4];

    static int smem_set = 0;
    if (!smem_set) {
        cudaFuncSetAttribute(attn_fused, cudaFuncAttributeMaxDynamicSharedMemorySize,
                             SMEM_FLOATS * (int)sizeof(float));
        smem_set = 1;
    }
    attn_fused<<<NBLK, NTHR, SMEM_FLOATS * sizeof(float)>>>(
        x, wq, wk, wv, wp, (float*)d_out);
}